// round 15
// baseline (speedup 1.0000x reference)
#include <cuda_runtime.h>
#include <cstdint>
#include <math.h>

// Problem dims (fixed by the dataset)
#define BB 32
#define TT 64
#define PP 2048
#define DD 32
#define DOB 16

#define PSEQ_ELEMS ((size_t)BB * TT * PP * DD)   // 134217728
#define TINYF      1.17549435e-38f
#define NLO        -0.99999994f                  // nextafterf(-1,0)
// gumbel value bounds (exact, f32): g in [-4.4698, 15.9424]
#define G_HI       16.0f
#define G_LO_PAD   4.5f

// ---------------- scratch (device globals: allocation-free) ----------------
__device__ float g_sv_val[BB * PP];   // logits, sorted descending per batch
__device__ int   g_sv_idx[BB * PP];   // original particle indices (same order)
__device__ float g_floor[BB];
__device__ int   g_idx[BB * PP];      // resampling indices

// ---------------- threefry2x32 (bit-exact JAX) ----------------
__host__ __device__ __forceinline__ void tf2x32(unsigned k0, unsigned k1,
                                                unsigned x0, unsigned x1,
                                                unsigned& o0, unsigned& o1) {
  unsigned ks2 = k0 ^ k1 ^ 0x1BD11BDAu;
#define TFROUND(r) { x0 += x1; x1 = (x1 << (r)) | (x1 >> (32 - (r))); x1 ^= x0; }
  x0 += k0; x1 += k1;
  TFROUND(13) TFROUND(15) TFROUND(26) TFROUND(6)
  x0 += k1;  x1 += ks2 + 1u;
  TFROUND(17) TFROUND(29) TFROUND(16) TFROUND(24)
  x0 += ks2; x1 += k0 + 2u;
  TFROUND(13) TFROUND(15) TFROUND(26) TFROUND(6)
  x0 += k0;  x1 += k1 + 3u;
  TFROUND(17) TFROUND(29) TFROUND(16) TFROUND(24)
  x0 += k1;  x1 += ks2 + 4u;
  TFROUND(13) TFROUND(15) TFROUND(26) TFROUND(6)
  x0 += ks2; x1 += k0 + 5u;
#undef TFROUND
  o0 = x0; o1 = x1;
}

// jax partitionable random_bits (32-bit, size < 2^32): bits[i] = o0 ^ o1 of
// threefry(key, hi32(i)=0, lo32(i)=i)
__device__ __forceinline__ unsigned pbits32(unsigned k0, unsigned k1, unsigned i) {
  unsigned o0, o1;
  tf2x32(k0, k1, 0u, i, o0, o1);
  return o0 ^ o1;
}

// uniform bits -> f in [0,1) exactly as jax._src.random._uniform
__device__ __forceinline__ float bits_to_f01(unsigned r) {
  return __uint_as_float((r >> 9) | 0x3f800000u) - 1.0f;  // exact ops
}

// gumbel from f: -log(-log(max(tiny, f + tiny)))   ((1-tiny) rounds to 1.0f)
__device__ __forceinline__ float gumbel_from_f(float f) {
  float u = fmaxf(TINYF, __fadd_rn(f, TINYF));
  float a = logf(u);            // libdevice logf == XLA log
  return -logf(-a);
}

// Provable cheap upper bound on gumbel(f):  g <= -log2(1-f)*ln2 + margin
__device__ __forceinline__ float gumbel_ub(float f) {
  float t = 1.0f - f;                               // exact
  int k = (__float_as_int(t) >> 23) - 127;          // unbiased exponent, <= 0
  return fmaf((float)(-k), 0.69314724f, 0.01f);     // 0.69314724 > ln2
}

// XLA ErfInv32 (Giles), separate mul/add like XLA emits (no fma contraction)
__device__ __forceinline__ float erfinv_xla(float x) {
  float w = -log1pf(-__fmul_rn(x, x));
  float p;
  if (w < 5.0f) {
    w = __fadd_rn(w, -2.5f);
    p = 2.81022636e-08f;
    p = __fadd_rn(3.43273939e-07f,  __fmul_rn(p, w));
    p = __fadd_rn(-3.5233877e-06f,  __fmul_rn(p, w));
    p = __fadd_rn(-4.39150654e-06f, __fmul_rn(p, w));
    p = __fadd_rn(0.00021858087f,   __fmul_rn(p, w));
    p = __fadd_rn(-0.00125372503f,  __fmul_rn(p, w));
    p = __fadd_rn(-0.00417768164f,  __fmul_rn(p, w));
    p = __fadd_rn(0.246640727f,     __fmul_rn(p, w));
    p = __fadd_rn(1.50140941f,      __fmul_rn(p, w));
  } else {
    w = __fadd_rn(sqrtf(w), -3.0f);
    p = -0.000200214257f;
    p = __fadd_rn(0.000100950558f,  __fmul_rn(p, w));
    p = __fadd_rn(0.00134934322f,   __fmul_rn(p, w));
    p = __fadd_rn(-0.00367342844f,  __fmul_rn(p, w));
    p = __fadd_rn(0.00573950773f,   __fmul_rn(p, w));
    p = __fadd_rn(-0.0076224613f,   __fmul_rn(p, w));
    p = __fadd_rn(0.00943887047f,   __fmul_rn(p, w));
    p = __fadd_rn(1.00167406f,      __fmul_rn(p, w));
    p = __fadd_rn(2.83297682f,      __fmul_rn(p, w));
  }
  return __fmul_rn(p, x);
}

// normal: u = max(lo, f*2 + lo); sqrt(2)*erfinv(u)   (hi-lo rounds to 2.0f)
__device__ __forceinline__ float normal_from_bits(unsigned r) {
  float f = bits_to_f01(r);
  float u = fmaxf(NLO, __fadd_rn(__fmul_rn(f, 2.0f), NLO));
  return __fmul_rn(1.41421354f, erfinv_xla(u));
}

// ---- kernel 1: normalize, then bitonic-sort logits DESCENDING ------------
__global__ void __launch_bounds__(512) normalize_kernel(const float* __restrict__ wseq, int t) {
  int b = blockIdx.x, tid = threadIdx.x;
  __shared__ float sl[PP];
  __shared__ int   sidx[PP];
  __shared__ float red[512];
  for (int p = tid; p < PP; p += 512)
    sl[p] = wseq[((size_t)b * TT + (t - 1)) * PP + p];
  __syncthreads();
  float m = -INFINITY;
  for (int p = tid; p < PP; p += 512) m = fmaxf(m, sl[p]);
  red[tid] = m; __syncthreads();
  for (int s = 256; s > 0; s >>= 1) { if (tid < s) red[tid] = fmaxf(red[tid], red[tid + s]); __syncthreads(); }
  m = red[0]; __syncthreads();
  float s = 0.0f;
  for (int p = tid; p < PP; p += 512) s += expf(sl[p] - m);
  red[tid] = s; __syncthreads();
  for (int k = 256; k > 0; k >>= 1) { if (tid < k) red[tid] += red[tid + k]; __syncthreads(); }
  float lse = logf(red[0]) + m;     // uniform shift: cancels in argmax
  float lmax = m - lse;             // max normalized logit
  if (tid == 0) g_floor[b] = lmax - G_LO_PAD;  // strict lower bound on winner
  __syncthreads();
  for (int p = tid; p < PP; p += 512) {
    sl[p] = fmaxf(__fsub_rn(sl[p], lse), -50.0f);
    sidx[p] = p;
  }
  __syncthreads();
  // Bitonic sort, descending by sl (scan order doesn't affect the argmax).
  for (int k = 2; k <= PP; k <<= 1) {
    for (int j = k >> 1; j > 0; j >>= 1) {
      for (int i = tid; i < PP; i += 512) {
        int ixj = i ^ j;
        if (ixj > i) {
          float a = sl[i], c = sl[ixj];
          bool desc = ((i & k) == 0);
          if (desc ? (a < c) : (a > c)) {
            sl[i] = c; sl[ixj] = a;
            int ti = sidx[i]; sidx[i] = sidx[ixj]; sidx[ixj] = ti;
          }
        }
      }
      __syncthreads();
    }
  }
  for (int p = tid; p < PP; p += 512) {
    g_sv_val[b * PP + p] = sl[p];
    g_sv_idx[b * PP + p] = sidx[p];
  }
}

// ---- kernel 2a: t=0 categorical. Uniform logits => integer argmax ========
__global__ void __launch_bounds__(256) categorical_t0_kernel(unsigned k0, unsigned k1) {
  int lane = threadIdx.x & 31;
  int pn   = blockIdx.x * 8 + (threadIdx.x >> 5);
  int b    = blockIdx.y;
  unsigned base = ((unsigned)(pn * BB + b)) << 11;  // * PP
  unsigned bm0 = 0, bm1 = 0;
  int bi0 = 0x7FFFFFFF, bi1 = 0x7FFFFFFF;
#pragma unroll 4
  for (int k = 0; k < PP / 2; k += 32) {      // two independent chains for ILP
    int p0 = lane + k, p1 = p0 + PP / 2;
    unsigned m0 = pbits32(k0, k1, base + (unsigned)p0) >> 9;
    unsigned m1 = pbits32(k0, k1, base + (unsigned)p1) >> 9;
    if (m0 > bm0 || (m0 == bm0 && p0 < bi0)) { bm0 = m0; bi0 = p0; }
    if (m1 > bm1 || (m1 == bm1 && p1 < bi1)) { bm1 = m1; bi1 = p1; }
  }
  if (bm1 > bm0 || (bm1 == bm0 && bi1 < bi0)) { bm0 = bm1; bi0 = bi1; }
#pragma unroll
  for (int off = 16; off > 0; off >>= 1) {
    unsigned om = __shfl_down_sync(0xFFFFFFFFu, bm0, off);
    int      oi = __shfl_down_sync(0xFFFFFFFFu, bi0, off);
    if (om > bm0 || (om == bm0 && oi < bi0)) { bm0 = om; bi0 = oi; }
  }
  if (lane == 0) g_idx[b * PP + pn] = bi0;
}

// ---- kernel 2b: t>=1 categorical, dual-chain scan with exact break -------
__global__ void __launch_bounds__(256) categorical_kernel(unsigned k0, unsigned k1) {
  __shared__ float sv[PP];
  __shared__ int   si[PP];
  int b   = blockIdx.y;
  int tid = threadIdx.x;
  for (int i = tid; i < PP; i += 256) {
    sv[i] = g_sv_val[b * PP + i];
    si[i] = g_sv_idx[b * PP + i];
  }
  __syncthreads();

  int lane = tid & 31;
  int pn   = blockIdx.x * 8 + (tid >> 5);
  unsigned base = ((unsigned)(pn * BB + b)) << 11;  // * PP
  float best = g_floor[b];
  int   bi = 0x7FFFFFFF;
  for (int s = 0; s < PP; s += 64) {
    int i0 = s + lane, i1 = i0 + 32;
    float l0 = sv[i0];
    bool a0 = __fadd_rn(l0, G_HI) > best;          // coarse bound
    if (!__any_sync(0xFFFFFFFFu, a0)) break;       // exact early exit (sorted)
    float l1 = sv[i1];
    bool a1 = __fadd_rn(l1, G_HI) > best;
    unsigned idx0 = (unsigned)si[i0];
    unsigned idx1 = (unsigned)si[i1];
    unsigned r0 = pbits32(k0, k1, base + idx0);    // dual independent chains
    unsigned r1 = pbits32(k0, k1, base + idx1);
    if (a0) {
      float f = bits_to_f01(r0);
      if (__fadd_rn(l0, gumbel_ub(f)) >= best) {   // fine bound (skips logf's)
        float v = __fadd_rn(gumbel_from_f(f), l0);
        if (v > best || (v == best && (int)idx0 < bi)) { best = v; bi = (int)idx0; }
      }
    }
    if (a1) {
      float f = bits_to_f01(r1);
      if (__fadd_rn(l1, gumbel_ub(f)) >= best) {
        float v = __fadd_rn(gumbel_from_f(f), l1);
        if (v > best || (v == best && (int)idx1 < bi)) { best = v; bi = (int)idx1; }
      }
    }
  }
#pragma unroll
  for (int off = 16; off > 0; off >>= 1) {
    float ov = __shfl_down_sync(0xFFFFFFFFu, best, off);
    int   oi = __shfl_down_sync(0xFFFFFFFFu, bi,   off);
    if (ov > best || (ov == best && oi < bi)) { best = ov; bi = oi; }
  }
  if (lane == 0) g_idx[b * PP + pn] = bi;
}

// ---- kernel 3: fused resample-gather + transition + measurement ----------
// PHASE-SEPARATED: all 32 normals are generated first as independent chains
// (threefry+erfinv have no cross-dim dependency), THEN the matvecs consume
// them. Same float ops, same rounding, same order per value => bit-identical;
// only the instruction schedule changes (8x more ILP on the long chains).
__global__ void __launch_bounds__(256) update_kernel(
    unsigned kn0, unsigned kn1, int t,
    const float* __restrict__ obs, const float* __restrict__ init_p,
    const float* __restrict__ A, const float* __restrict__ bvec,
    const float* __restrict__ log_sigma, const float* __restrict__ Cm,
    const float* __restrict__ log_r,
    float* __restrict__ pseq, float* __restrict__ wseq, float c8) {
  __shared__ float4 sA[DD * DD / 4];   // 256 float4
  __shared__ float4 sC[DOB * DD / 4];  // 128 float4
  __shared__ float s_sig[DD], s_er[DOB];
  __shared__ float s_slr;
  int tid = threadIdx.x;
  for (int i = tid; i < DD * DD / 4; i += 256) sA[i] = ((const float4*)A)[i];
  for (int i = tid; i < DOB * DD / 4; i += 256) sC[i] = ((const float4*)Cm)[i];
  if (tid < DD)  s_sig[tid] = expf(log_sigma[tid]);
  if (tid < DOB) s_er[tid]  = expf(-log_r[tid]);
  if (tid == 0) {
    float a = 0.0f;
#pragma unroll
    for (int o = 0; o < DOB; ++o) a = __fadd_rn(a, log_r[o]);
    s_slr = a;
  }
  __syncthreads();

  int gid = blockIdx.x * 256 + tid;
  int b = gid >> 11;
  int p = gid & (PP - 1);
  int j = g_idx[b * PP + p];
  const float4* src4 = (t == 0)
      ? (const float4*)(init_p + ((size_t)b * PP + j) * DD)
      : (const float4*)(pseq + (((size_t)b * TT + (t - 1)) * PP + j) * DD);
  float x[DD];
#pragma unroll
  for (int q = 0; q < DD / 4; ++q) {
    float4 v = src4[q];
    x[4 * q] = v.x; x[4 * q + 1] = v.y; x[4 * q + 2] = v.z; x[4 * q + 3] = v.w;
  }

  // ---- phase 1: 32 independent normal draws (max ILP) ----
  float n[DD];
  unsigned ibase = ((unsigned)(b * PP + p)) * DD;
#pragma unroll
  for (int e = 0; e < DD; ++e)
    n[e] = normal_from_bits(pbits32(kn0, kn1, ibase + (unsigned)e));

  // ---- phase 2: transition matvec + combine (identical value path) ----
  float xn[DD];
#pragma unroll
  for (int e = 0; e < DD; ++e) {
    float mv = 0.0f;
#pragma unroll
    for (int q = 0; q < DD / 4; ++q) {
      float4 a = sA[e * (DD / 4) + q];
      mv = fmaf(x[4 * q],     a.x, mv);
      mv = fmaf(x[4 * q + 1], a.y, mv);
      mv = fmaf(x[4 * q + 2], a.z, mv);
      mv = fmaf(x[4 * q + 3], a.w, mv);
    }
    // ((dot + b) + noise*sigma): separate roundings, left-assoc like XLA
    xn[e] = __fadd_rn(__fadd_rn(mv, bvec[e]), __fmul_rn(n[e], s_sig[e]));
  }
  float4* out4 = (float4*)(pseq + (((size_t)b * TT + t) * PP + p) * DD);
#pragma unroll
  for (int q = 0; q < DD / 4; ++q)
    out4[q] = make_float4(xn[4 * q], xn[4 * q + 1], xn[4 * q + 2], xn[4 * q + 3]);

  const float* y = obs + ((size_t)b * TT + t) * DOB;
  float ss = 0.0f;
#pragma unroll
  for (int o = 0; o < DOB; ++o) {
    float mean = 0.0f;
#pragma unroll
    for (int q = 0; q < DD / 4; ++q) {
      float4 c = sC[o * (DD / 4) + q];
      mean = fmaf(xn[4 * q],     c.x, mean);
      mean = fmaf(xn[4 * q + 1], c.y, mean);
      mean = fmaf(xn[4 * q + 2], c.z, mean);
      mean = fmaf(xn[4 * q + 3], c.w, mean);
    }
    float rr = __fmul_rn(__fsub_rn(y[o], mean), s_er[o]);
    ss = __fadd_rn(ss, __fmul_rn(rr, rr));
  }
  float logw = __fsub_rn(__fsub_rn(__fmul_rn(-0.5f, ss), s_slr), c8);
  wseq[((size_t)b * TT + t) * PP + p] = logw;
}

// ---------------- host ----------------
extern "C" void kernel_launch(void* const* d_in, const int* in_sizes, int n_in,
                              void* d_out, int out_size) {
  (void)out_size;
  // Dispatch inputs by element count (robust to metadata ordering).
  const float *obs = 0, *init_p = 0, *A = 0, *bvec = 0, *lsig = 0, *Cm = 0, *lr = 0;
  for (int i = 0; i < n_in; ++i) {
    const float* ptr = (const float*)d_in[i];
    switch (in_sizes[i]) {
      case BB * TT * DOB:      obs = ptr;    break;  // 32768
      case BB * PP * DD:       init_p = ptr; break;  // 2097152
      case DD * DD:            A = ptr;      break;  // 1024
      case DOB * DD:           Cm = ptr;     break;  // 512
      case DOB:                lr = ptr;     break;  // 16
      case DD:  if (!bvec) bvec = ptr; else lsig = ptr; break;  // b, log_sigma
      default: break;
    }
  }
  float* pseq = (float*)d_out;
  float* wseq = pseq + PSEQ_ELEMS;

  // 0.5 * dim_obs * log(2*pi), f32 pipeline like XLA's constant folding
  float log2pi = logf(6.2831855f);
  float c8     = 8.0f * log2pi;

  for (int t = 0; t < TT; ++t) {
    // k = fold_in(key(42), t) = threefry((0,42),(0,t))
    unsigned h0, h1;
    tf2x32(0u, 42u, 0u, (unsigned)t, h0, h1);
    // partitionable foldlike split: key_i = threefry(k, (0, i)) both words
    unsigned r0a, r0b, r1a, r1b;
    tf2x32(h0, h1, 0u, 0u, r0a, r0b);   // k_res   = (r0a, r0b)
    tf2x32(h0, h1, 0u, 1u, r1a, r1b);   // k_noise = (r1a, r1b)

    if (t == 0) {
      categorical_t0_kernel<<<dim3(PP / 8, BB), 256>>>(r0a, r0b);
    } else {
      normalize_kernel<<<BB, 512>>>(wseq, t);
      categorical_kernel<<<dim3(PP / 8, BB), 256>>>(r0a, r0b);
    }
    update_kernel<<<(BB * PP) / 256, 256>>>(r1a, r1b, t, obs, init_p, A, bvec,
                                            lsig, Cm, lr, pseq, wseq, c8);
  }
}

// round 16
// speedup vs baseline: 1.0169x; 1.0169x over previous
#include <cuda_runtime.h>
#include <cstdint>
#include <math.h>

// Problem dims (fixed by the dataset)
#define BB 32
#define TT 64
#define PP 2048
#define DD 32
#define DOB 16

#define PSEQ_ELEMS ((size_t)BB * TT * PP * DD)   // 134217728
#define TINYF      1.17549435e-38f
#define NLO        -0.99999994f                  // nextafterf(-1,0)
// gumbel value bounds (exact, f32): g in [-4.4698, 15.9424]
#define G_HI       16.0f
#define G_LO_PAD   4.5f
#define NBUCK      64
#define BW         0.25f                         // bucket width (power of two)

// ---------------- scratch (device globals: allocation-free) ----------------
__device__ float2 g_sv_lu[BB * PP];   // (logit, position-upper-bound), bucket-desc order
__device__ int    g_sv_idx[BB * PP];  // original particle indices (same order)
__device__ float  g_floor[BB];
__device__ int    g_idx[BB * PP];     // resampling indices

// ---------------- threefry2x32 (bit-exact JAX) ----------------
__host__ __device__ __forceinline__ void tf2x32(unsigned k0, unsigned k1,
                                                unsigned x0, unsigned x1,
                                                unsigned& o0, unsigned& o1) {
  unsigned ks2 = k0 ^ k1 ^ 0x1BD11BDAu;
#define TFROUND(r) { x0 += x1; x1 = (x1 << (r)) | (x1 >> (32 - (r))); x1 ^= x0; }
  x0 += k0; x1 += k1;
  TFROUND(13) TFROUND(15) TFROUND(26) TFROUND(6)
  x0 += k1;  x1 += ks2 + 1u;
  TFROUND(17) TFROUND(29) TFROUND(16) TFROUND(24)
  x0 += ks2; x1 += k0 + 2u;
  TFROUND(13) TFROUND(15) TFROUND(26) TFROUND(6)
  x0 += k0;  x1 += k1 + 3u;
  TFROUND(17) TFROUND(29) TFROUND(16) TFROUND(24)
  x0 += k1;  x1 += ks2 + 4u;
  TFROUND(13) TFROUND(15) TFROUND(26) TFROUND(6)
  x0 += ks2; x1 += k0 + 5u;
#undef TFROUND
  o0 = x0; o1 = x1;
}

// jax partitionable random_bits (32-bit, size < 2^32): bits[i] = o0 ^ o1 of
// threefry(key, hi32(i)=0, lo32(i)=i)
__device__ __forceinline__ unsigned pbits32(unsigned k0, unsigned k1, unsigned i) {
  unsigned o0, o1;
  tf2x32(k0, k1, 0u, i, o0, o1);
  return o0 ^ o1;
}

// uniform bits -> f in [0,1) exactly as jax._src.random._uniform
__device__ __forceinline__ float bits_to_f01(unsigned r) {
  return __uint_as_float((r >> 9) | 0x3f800000u) - 1.0f;  // exact ops
}

// gumbel from f: -log(-log(max(tiny, f + tiny)))   ((1-tiny) rounds to 1.0f)
__device__ __forceinline__ float gumbel_from_f(float f) {
  float u = fmaxf(TINYF, __fadd_rn(f, TINYF));
  float a = logf(u);            // libdevice logf == XLA log
  return -logf(-a);
}

// Provable cheap upper bound on gumbel(f):  g <= -log2(1-f)*ln2 + margin
__device__ __forceinline__ float gumbel_ub(float f) {
  float t = 1.0f - f;                               // exact
  int k = (__float_as_int(t) >> 23) - 127;          // unbiased exponent, <= 0
  return fmaf((float)(-k), 0.69314724f, 0.01f);     // 0.69314724 > ln2
}

// XLA ErfInv32 (Giles), separate mul/add like XLA emits (no fma contraction)
__device__ __forceinline__ float erfinv_xla(float x) {
  float w = -log1pf(-__fmul_rn(x, x));
  float p;
  if (w < 5.0f) {
    w = __fadd_rn(w, -2.5f);
    p = 2.81022636e-08f;
    p = __fadd_rn(3.43273939e-07f,  __fmul_rn(p, w));
    p = __fadd_rn(-3.5233877e-06f,  __fmul_rn(p, w));
    p = __fadd_rn(-4.39150654e-06f, __fmul_rn(p, w));
    p = __fadd_rn(0.00021858087f,   __fmul_rn(p, w));
    p = __fadd_rn(-0.00125372503f,  __fmul_rn(p, w));
    p = __fadd_rn(-0.00417768164f,  __fmul_rn(p, w));
    p = __fadd_rn(0.246640727f,     __fmul_rn(p, w));
    p = __fadd_rn(1.50140941f,      __fmul_rn(p, w));
  } else {
    w = __fadd_rn(sqrtf(w), -3.0f);
    p = -0.000200214257f;
    p = __fadd_rn(0.000100950558f,  __fmul_rn(p, w));
    p = __fadd_rn(0.00134934322f,   __fmul_rn(p, w));
    p = __fadd_rn(-0.00367342844f,  __fmul_rn(p, w));
    p = __fadd_rn(0.00573950773f,   __fmul_rn(p, w));
    p = __fadd_rn(-0.0076224613f,   __fmul_rn(p, w));
    p = __fadd_rn(0.00943887047f,   __fmul_rn(p, w));
    p = __fadd_rn(1.00167406f,      __fmul_rn(p, w));
    p = __fadd_rn(2.83297682f,      __fmul_rn(p, w));
  }
  return __fmul_rn(p, x);
}

// normal: u = max(lo, f*2 + lo); sqrt(2)*erfinv(u)   (hi-lo rounds to 2.0f)
__device__ __forceinline__ float normal_from_bits(unsigned r) {
  float f = bits_to_f01(r);
  float u = fmaxf(NLO, __fadd_rn(__fmul_rn(f, 2.0f), NLO));
  return __fmul_rn(1.41421354f, erfinv_xla(u));
}

// ---- kernel 1: normalize + counting sort into 64 descending-l buckets ----
// Replaces the bitonic sort (66 barrier phases) with histogram+prefix+scatter
// (4 barriers). Order within a bucket is arbitrary (argmax comparator is
// order-independent); the categorical break uses the per-position upper
// bound ub = lmax - q*BW + 1e-3 which is monotone non-increasing and >= l.
__global__ void __launch_bounds__(512) normalize_kernel(const float* __restrict__ wseq, int t) {
  int b = blockIdx.x, tid = threadIdx.x;
  __shared__ float red[512];
  __shared__ int hist[NBUCK];
  __shared__ int boff[NBUCK];
  float w[PP / 512];
#pragma unroll
  for (int k = 0; k < PP / 512; ++k)
    w[k] = wseq[((size_t)b * TT + (t - 1)) * PP + tid + k * 512];
  float m = -INFINITY;
#pragma unroll
  for (int k = 0; k < PP / 512; ++k) m = fmaxf(m, w[k]);
  red[tid] = m; __syncthreads();
  for (int s = 256; s > 0; s >>= 1) { if (tid < s) red[tid] = fmaxf(red[tid], red[tid + s]); __syncthreads(); }
  m = red[0]; __syncthreads();
  float s = 0.0f;
#pragma unroll
  for (int k = 0; k < PP / 512; ++k) s += expf(w[k] - m);
  red[tid] = s; __syncthreads();
  for (int k = 256; k > 0; k >>= 1) { if (tid < k) red[tid] += red[tid + k]; __syncthreads(); }
  float lse = logf(red[0]) + m;     // uniform shift: cancels in argmax
  float lmax = m - lse;             // max normalized logit
  if (tid == 0) g_floor[b] = lmax - G_LO_PAD;  // strict lower bound on winner
  if (tid < NBUCK) hist[tid] = 0;
  __syncthreads();
  float l[PP / 512];
  int   q[PP / 512];
#pragma unroll
  for (int k = 0; k < PP / 512; ++k) {
    l[k] = fmaxf(__fsub_rn(w[k], lse), -50.0f);
    float d = __fsub_rn(lmax, l[k]);            // >= 0
    int qq = (int)(d * 4.0f);                   // exact: 4d truncated
    q[k] = qq > (NBUCK - 1) ? (NBUCK - 1) : qq;
    atomicAdd(&hist[q[k]], 1);
  }
  __syncthreads();
  // exclusive prefix over 64 buckets (single warp)
  if (tid < 32) {
    int v0 = hist[tid], v1 = hist[tid + 32];
    // scan 64 values with one warp: serial-ish but tiny
    if (tid == 0) {
      int acc = 0;
#pragma unroll
      for (int i = 0; i < NBUCK; ++i) { int h = hist[i]; boff[i] = acc; acc += h; }
    }
    (void)v0; (void)v1;
  }
  __syncthreads();
#pragma unroll
  for (int k = 0; k < PP / 512; ++k) {
    int pos = atomicAdd(&boff[q[k]], 1);
    // ub >= l (exact-safe margin), monotone non-increasing across positions
    float ub = __fadd_rn(__fsub_rn(lmax, (float)q[k] * BW), 0.001f);
    g_sv_lu[b * PP + pos] = make_float2(l[k], ub);
    g_sv_idx[b * PP + pos] = tid + k * 512;
  }
}

// ---- kernel 2a: t=0 categorical. Uniform logits => integer argmax ========
__global__ void __launch_bounds__(256) categorical_t0_kernel(unsigned k0, unsigned k1) {
  int lane = threadIdx.x & 31;
  int pn   = blockIdx.x * 8 + (threadIdx.x >> 5);
  int b    = blockIdx.y;
  unsigned base = ((unsigned)(pn * BB + b)) << 11;  // * PP
  unsigned bm0 = 0, bm1 = 0;
  int bi0 = 0x7FFFFFFF, bi1 = 0x7FFFFFFF;
#pragma unroll 4
  for (int k = 0; k < PP / 2; k += 32) {      // two independent chains for ILP
    int p0 = lane + k, p1 = p0 + PP / 2;
    unsigned m0 = pbits32(k0, k1, base + (unsigned)p0) >> 9;
    unsigned m1 = pbits32(k0, k1, base + (unsigned)p1) >> 9;
    if (m0 > bm0 || (m0 == bm0 && p0 < bi0)) { bm0 = m0; bi0 = p0; }
    if (m1 > bm1 || (m1 == bm1 && p1 < bi1)) { bm1 = m1; bi1 = p1; }
  }
  if (bm1 > bm0 || (bm1 == bm0 && bi1 < bi0)) { bm0 = bm1; bi0 = bi1; }
#pragma unroll
  for (int off = 16; off > 0; off >>= 1) {
    unsigned om = __shfl_down_sync(0xFFFFFFFFu, bm0, off);
    int      oi = __shfl_down_sync(0xFFFFFFFFu, bi0, off);
    if (om > bm0 || (om == bm0 && oi < bi0)) { bm0 = om; bi0 = oi; }
  }
  if (lane == 0) g_idx[b * PP + pn] = bi0;
}

// ---- kernel 2b: t>=1 categorical, dual-chain scan with exact break -------
// Per-lane hash-skip uses EXACT l; the warp break uses the monotone ub.
__global__ void __launch_bounds__(256) categorical_kernel(unsigned k0, unsigned k1) {
  __shared__ float2 sv[PP];
  __shared__ int    si[PP];
  int b   = blockIdx.y;
  int tid = threadIdx.x;
  for (int i = tid; i < PP; i += 256) {
    sv[i] = g_sv_lu[b * PP + i];
    si[i] = g_sv_idx[b * PP + i];
  }
  __syncthreads();

  int lane = tid & 31;
  int pn   = blockIdx.x * 8 + (tid >> 5);
  unsigned base = ((unsigned)(pn * BB + b)) << 11;  // * PP
  float best = g_floor[b];
  int   bi = 0x7FFFFFFF;
  for (int s = 0; s < PP; s += 64) {
    int i0 = s + lane, i1 = i0 + 32;
    float2 lu0 = sv[i0];
    // break: ub monotone non-increasing => if every lane's ub fails, all
    // later positions fail (g < 16 strictly) — exact early exit.
    if (!__any_sync(0xFFFFFFFFu, __fadd_rn(lu0.y, G_HI) > best)) break;
    float l0 = lu0.x;
    float2 lu1 = sv[i1];
    float l1 = lu1.x;
    bool a0 = __fadd_rn(l0, G_HI) > best;          // exact per-lane bound
    bool a1 = __fadd_rn(l1, G_HI) > best;
    unsigned idx0 = (unsigned)si[i0];
    unsigned idx1 = (unsigned)si[i1];
    unsigned r0 = pbits32(k0, k1, base + idx0);    // dual independent chains
    unsigned r1 = pbits32(k0, k1, base + idx1);
    if (a0) {
      float f = bits_to_f01(r0);
      if (__fadd_rn(l0, gumbel_ub(f)) >= best) {   // fine bound (skips logf's)
        float v = __fadd_rn(gumbel_from_f(f), l0);
        if (v > best || (v == best && (int)idx0 < bi)) { best = v; bi = (int)idx0; }
      }
    }
    if (a1) {
      float f = bits_to_f01(r1);
      if (__fadd_rn(l1, gumbel_ub(f)) >= best) {
        float v = __fadd_rn(gumbel_from_f(f), l1);
        if (v > best || (v == best && (int)idx1 < bi)) { best = v; bi = (int)idx1; }
      }
    }
  }
#pragma unroll
  for (int off = 16; off > 0; off >>= 1) {
    float ov = __shfl_down_sync(0xFFFFFFFFu, best, off);
    int   oi = __shfl_down_sync(0xFFFFFFFFu, bi,   off);
    if (ov > best || (ov == best && oi < bi)) { best = ov; bi = oi; }
  }
  if (lane == 0) g_idx[b * PP + pn] = bi;
}

// ---- kernel 3: fused resample-gather + transition + measurement ----------
// (R14 form: interleaved normal generation — the measured-fastest variant.)
__global__ void __launch_bounds__(256) update_kernel(
    unsigned kn0, unsigned kn1, int t,
    const float* __restrict__ obs, const float* __restrict__ init_p,
    const float* __restrict__ A, const float* __restrict__ bvec,
    const float* __restrict__ log_sigma, const float* __restrict__ Cm,
    const float* __restrict__ log_r,
    float* __restrict__ pseq, float* __restrict__ wseq, float c8) {
  __shared__ float4 sA[DD * DD / 4];   // 256 float4
  __shared__ float4 sC[DOB * DD / 4];  // 128 float4
  __shared__ float s_sig[DD], s_er[DOB];
  __shared__ float s_slr;
  int tid = threadIdx.x;
  for (int i = tid; i < DD * DD / 4; i += 256) sA[i] = ((const float4*)A)[i];
  for (int i = tid; i < DOB * DD / 4; i += 256) sC[i] = ((const float4*)Cm)[i];
  if (tid < DD)  s_sig[tid] = expf(log_sigma[tid]);
  if (tid < DOB) s_er[tid]  = expf(-log_r[tid]);
  if (tid == 0) {
    float a = 0.0f;
#pragma unroll
    for (int o = 0; o < DOB; ++o) a = __fadd_rn(a, log_r[o]);
    s_slr = a;
  }
  __syncthreads();

  int gid = blockIdx.x * 256 + tid;
  int b = gid >> 11;
  int p = gid & (PP - 1);
  int j = g_idx[b * PP + p];
  const float4* src4 = (t == 0)
      ? (const float4*)(init_p + ((size_t)b * PP + j) * DD)
      : (const float4*)(pseq + (((size_t)b * TT + (t - 1)) * PP + j) * DD);
  float x[DD];
#pragma unroll
  for (int q = 0; q < DD / 4; ++q) {
    float4 v = src4[q];
    x[4 * q] = v.x; x[4 * q + 1] = v.y; x[4 * q + 2] = v.z; x[4 * q + 3] = v.w;
  }

  float xn[DD];
  unsigned ibase = ((unsigned)(b * PP + p)) * DD;
#pragma unroll 4
  for (int e = 0; e < DD; ++e) {
    float mv = 0.0f;
#pragma unroll
    for (int q = 0; q < DD / 4; ++q) {
      float4 a = sA[e * (DD / 4) + q];
      mv = fmaf(x[4 * q],     a.x, mv);
      mv = fmaf(x[4 * q + 1], a.y, mv);
      mv = fmaf(x[4 * q + 2], a.z, mv);
      mv = fmaf(x[4 * q + 3], a.w, mv);
    }
    float n = normal_from_bits(pbits32(kn0, kn1, ibase + (unsigned)e));
    // ((dot + b) + noise*sigma): separate roundings, left-assoc like XLA
    xn[e] = __fadd_rn(__fadd_rn(mv, bvec[e]), __fmul_rn(n, s_sig[e]));
  }
  float4* out4 = (float4*)(pseq + (((size_t)b * TT + t) * PP + p) * DD);
#pragma unroll
  for (int q = 0; q < DD / 4; ++q)
    out4[q] = make_float4(xn[4 * q], xn[4 * q + 1], xn[4 * q + 2], xn[4 * q + 3]);

  const float* y = obs + ((size_t)b * TT + t) * DOB;
  float ss = 0.0f;
#pragma unroll
  for (int o = 0; o < DOB; ++o) {
    float mean = 0.0f;
#pragma unroll
    for (int q = 0; q < DD / 4; ++q) {
      float4 c = sC[o * (DD / 4) + q];
      mean = fmaf(xn[4 * q],     c.x, mean);
      mean = fmaf(xn[4 * q + 1], c.y, mean);
      mean = fmaf(xn[4 * q + 2], c.z, mean);
      mean = fmaf(xn[4 * q + 3], c.w, mean);
    }
    float rr = __fmul_rn(__fsub_rn(y[o], mean), s_er[o]);
    ss = __fadd_rn(ss, __fmul_rn(rr, rr));
  }
  float logw = __fsub_rn(__fsub_rn(__fmul_rn(-0.5f, ss), s_slr), c8);
  wseq[((size_t)b * TT + t) * PP + p] = logw;
}

// ---------------- host ----------------
extern "C" void kernel_launch(void* const* d_in, const int* in_sizes, int n_in,
                              void* d_out, int out_size) {
  (void)out_size;
  // Dispatch inputs by element count (robust to metadata ordering).
  const float *obs = 0, *init_p = 0, *A = 0, *bvec = 0, *lsig = 0, *Cm = 0, *lr = 0;
  for (int i = 0; i < n_in; ++i) {
    const float* ptr = (const float*)d_in[i];
    switch (in_sizes[i]) {
      case BB * TT * DOB:      obs = ptr;    break;  // 32768
      case BB * PP * DD:       init_p = ptr; break;  // 2097152
      case DD * DD:            A = ptr;      break;  // 1024
      case DOB * DD:           Cm = ptr;     break;  // 512
      case DOB:                lr = ptr;     break;  // 16
      case DD:  if (!bvec) bvec = ptr; else lsig = ptr; break;  // b, log_sigma
      default: break;
    }
  }
  float* pseq = (float*)d_out;
  float* wseq = pseq + PSEQ_ELEMS;

  // 0.5 * dim_obs * log(2*pi), f32 pipeline like XLA's constant folding
  float log2pi = logf(6.2831855f);
  float c8     = 8.0f * log2pi;

  for (int t = 0; t < TT; ++t) {
    // k = fold_in(key(42), t) = threefry((0,42),(0,t))
    unsigned h0, h1;
    tf2x32(0u, 42u, 0u, (unsigned)t, h0, h1);
    // partitionable foldlike split: key_i = threefry(k, (0, i)) both words
    unsigned r0a, r0b, r1a, r1b;
    tf2x32(h0, h1, 0u, 0u, r0a, r0b);   // k_res   = (r0a, r0b)
    tf2x32(h0, h1, 0u, 1u, r1a, r1b);   // k_noise = (r1a, r1b)

    if (t == 0) {
      categorical_t0_kernel<<<dim3(PP / 8, BB), 256>>>(r0a, r0b);
    } else {
      normalize_kernel<<<BB, 512>>>(wseq, t);
      categorical_kernel<<<dim3(PP / 8, BB), 256>>>(r0a, r0b);
    }
    update_kernel<<<(BB * PP) / 256, 256>>>(r1a, r1b, t, obs, init_p, A, bvec,
                                            lsig, Cm, lr, pseq, wseq, c8);
  }
}

// round 17
// speedup vs baseline: 1.0577x; 1.0402x over previous
#include <cuda_runtime.h>
#include <cstdint>
#include <math.h>

// Problem dims (fixed by the dataset)
#define BB 32
#define TT 64
#define PP 2048
#define DD 32
#define DOB 16

#define PSEQ_ELEMS ((size_t)BB * TT * PP * DD)   // 134217728
#define TINYF      1.17549435e-38f
#define NLO        -0.99999994f                  // nextafterf(-1,0)
// gumbel value bounds (exact, f32): g in [-4.4698, 15.9424]
#define G_HI       16.0f
#define G_LO_PAD   4.5f

// ---------------- scratch (device globals: allocation-free) ----------------
__device__ float g_sv_val[BB * PP];   // logits, sorted descending per batch
__device__ int   g_sv_idx[BB * PP];   // original particle indices (same order)
__device__ float g_floor[BB];
__device__ int   g_idx[BB * PP];      // resampling indices

// ---------------- threefry2x32 (bit-exact JAX) ----------------
__host__ __device__ __forceinline__ void tf2x32(unsigned k0, unsigned k1,
                                                unsigned x0, unsigned x1,
                                                unsigned& o0, unsigned& o1) {
  unsigned ks2 = k0 ^ k1 ^ 0x1BD11BDAu;
#define TFROUND(r) { x0 += x1; x1 = (x1 << (r)) | (x1 >> (32 - (r))); x1 ^= x0; }
  x0 += k0; x1 += k1;
  TFROUND(13) TFROUND(15) TFROUND(26) TFROUND(6)
  x0 += k1;  x1 += ks2 + 1u;
  TFROUND(17) TFROUND(29) TFROUND(16) TFROUND(24)
  x0 += ks2; x1 += k0 + 2u;
  TFROUND(13) TFROUND(15) TFROUND(26) TFROUND(6)
  x0 += k0;  x1 += k1 + 3u;
  TFROUND(17) TFROUND(29) TFROUND(16) TFROUND(24)
  x0 += k1;  x1 += ks2 + 4u;
  TFROUND(13) TFROUND(15) TFROUND(26) TFROUND(6)
  x0 += ks2; x1 += k0 + 5u;
#undef TFROUND
  o0 = x0; o1 = x1;
}

// jax partitionable random_bits (32-bit, size < 2^32): bits[i] = o0 ^ o1 of
// threefry(key, hi32(i)=0, lo32(i)=i)
__device__ __forceinline__ unsigned pbits32(unsigned k0, unsigned k1, unsigned i) {
  unsigned o0, o1;
  tf2x32(k0, k1, 0u, i, o0, o1);
  return o0 ^ o1;
}

// uniform bits -> f in [0,1) exactly as jax._src.random._uniform
__device__ __forceinline__ float bits_to_f01(unsigned r) {
  return __uint_as_float((r >> 9) | 0x3f800000u) - 1.0f;  // exact ops
}

// gumbel from f: -log(-log(max(tiny, f + tiny)))   ((1-tiny) rounds to 1.0f)
__device__ __forceinline__ float gumbel_from_f(float f) {
  float u = fmaxf(TINYF, __fadd_rn(f, TINYF));
  float a = logf(u);            // libdevice logf == XLA log
  return -logf(-a);
}

// Provable cheap upper bound on gumbel(f):  g <= -log2(1-f)*ln2 + margin
__device__ __forceinline__ float gumbel_ub(float f) {
  float t = 1.0f - f;                               // exact
  int k = (__float_as_int(t) >> 23) - 127;          // unbiased exponent, <= 0
  return fmaf((float)(-k), 0.69314724f, 0.01f);     // 0.69314724 > ln2
}

// XLA ErfInv32 (Giles), separate mul/add like XLA emits (no fma contraction)
__device__ __forceinline__ float erfinv_xla(float x) {
  float w = -log1pf(-__fmul_rn(x, x));
  float p;
  if (w < 5.0f) {
    w = __fadd_rn(w, -2.5f);
    p = 2.81022636e-08f;
    p = __fadd_rn(3.43273939e-07f,  __fmul_rn(p, w));
    p = __fadd_rn(-3.5233877e-06f,  __fmul_rn(p, w));
    p = __fadd_rn(-4.39150654e-06f, __fmul_rn(p, w));
    p = __fadd_rn(0.00021858087f,   __fmul_rn(p, w));
    p = __fadd_rn(-0.00125372503f,  __fmul_rn(p, w));
    p = __fadd_rn(-0.00417768164f,  __fmul_rn(p, w));
    p = __fadd_rn(0.246640727f,     __fmul_rn(p, w));
    p = __fadd_rn(1.50140941f,      __fmul_rn(p, w));
  } else {
    w = __fadd_rn(sqrtf(w), -3.0f);
    p = -0.000200214257f;
    p = __fadd_rn(0.000100950558f,  __fmul_rn(p, w));
    p = __fadd_rn(0.00134934322f,   __fmul_rn(p, w));
    p = __fadd_rn(-0.00367342844f,  __fmul_rn(p, w));
    p = __fadd_rn(0.00573950773f,   __fmul_rn(p, w));
    p = __fadd_rn(-0.0076224613f,   __fmul_rn(p, w));
    p = __fadd_rn(0.00943887047f,   __fmul_rn(p, w));
    p = __fadd_rn(1.00167406f,      __fmul_rn(p, w));
    p = __fadd_rn(2.83297682f,      __fmul_rn(p, w));
  }
  return __fmul_rn(p, x);
}

// normal: u = max(lo, f*2 + lo); sqrt(2)*erfinv(u)   (hi-lo rounds to 2.0f)
__device__ __forceinline__ float normal_from_bits(unsigned r) {
  float f = bits_to_f01(r);
  float u = fmaxf(NLO, __fadd_rn(__fmul_rn(f, 2.0f), NLO));
  return __fmul_rn(1.41421354f, erfinv_xla(u));
}

// ---- kernel 1: normalize, then bitonic-sort logits DESCENDING ------------
// (R14 form — the measured-best variant.)
__global__ void __launch_bounds__(512) normalize_kernel(const float* __restrict__ wseq, int t) {
  int b = blockIdx.x, tid = threadIdx.x;
  __shared__ float sl[PP];
  __shared__ int   sidx[PP];
  __shared__ float red[512];
  for (int p = tid; p < PP; p += 512)
    sl[p] = wseq[((size_t)b * TT + (t - 1)) * PP + p];
  __syncthreads();
  float m = -INFINITY;
  for (int p = tid; p < PP; p += 512) m = fmaxf(m, sl[p]);
  red[tid] = m; __syncthreads();
  for (int s = 256; s > 0; s >>= 1) { if (tid < s) red[tid] = fmaxf(red[tid], red[tid + s]); __syncthreads(); }
  m = red[0]; __syncthreads();
  float s = 0.0f;
  for (int p = tid; p < PP; p += 512) s += expf(sl[p] - m);
  red[tid] = s; __syncthreads();
  for (int k = 256; k > 0; k >>= 1) { if (tid < k) red[tid] += red[tid + k]; __syncthreads(); }
  float lse = logf(red[0]) + m;     // uniform shift: cancels in argmax
  float lmax = m - lse;             // max normalized logit
  if (tid == 0) g_floor[b] = lmax - G_LO_PAD;  // strict lower bound on winner
  __syncthreads();
  for (int p = tid; p < PP; p += 512) {
    sl[p] = fmaxf(__fsub_rn(sl[p], lse), -50.0f);
    sidx[p] = p;
  }
  __syncthreads();
  // Bitonic sort, descending by sl (scan order doesn't affect the argmax).
  for (int k = 2; k <= PP; k <<= 1) {
    for (int j = k >> 1; j > 0; j >>= 1) {
      for (int i = tid; i < PP; i += 512) {
        int ixj = i ^ j;
        if (ixj > i) {
          float a = sl[i], c = sl[ixj];
          bool desc = ((i & k) == 0);
          if (desc ? (a < c) : (a > c)) {
            sl[i] = c; sl[ixj] = a;
            int ti = sidx[i]; sidx[i] = sidx[ixj]; sidx[ixj] = ti;
          }
        }
      }
      __syncthreads();
    }
  }
  for (int p = tid; p < PP; p += 512) {
    g_sv_val[b * PP + p] = sl[p];
    g_sv_idx[b * PP + p] = sidx[p];
  }
}

// ---- kernel 2a: t=0 categorical. Uniform logits => integer argmax ========
__global__ void __launch_bounds__(256) categorical_t0_kernel(unsigned k0, unsigned k1) {
  int lane = threadIdx.x & 31;
  int pn   = blockIdx.x * 8 + (threadIdx.x >> 5);
  int b    = blockIdx.y;
  unsigned base = ((unsigned)(pn * BB + b)) << 11;  // * PP
  unsigned bm0 = 0, bm1 = 0;
  int bi0 = 0x7FFFFFFF, bi1 = 0x7FFFFFFF;
#pragma unroll 4
  for (int k = 0; k < PP / 2; k += 32) {      // two independent chains for ILP
    int p0 = lane + k, p1 = p0 + PP / 2;
    unsigned m0 = pbits32(k0, k1, base + (unsigned)p0) >> 9;
    unsigned m1 = pbits32(k0, k1, base + (unsigned)p1) >> 9;
    if (m0 > bm0 || (m0 == bm0 && p0 < bi0)) { bm0 = m0; bi0 = p0; }
    if (m1 > bm1 || (m1 == bm1 && p1 < bi1)) { bm1 = m1; bi1 = p1; }
  }
  if (bm1 > bm0 || (bm1 == bm0 && bi1 < bi0)) { bm0 = bm1; bi0 = bi1; }
#pragma unroll
  for (int off = 16; off > 0; off >>= 1) {
    unsigned om = __shfl_down_sync(0xFFFFFFFFu, bm0, off);
    int      oi = __shfl_down_sync(0xFFFFFFFFu, bi0, off);
    if (om > bm0 || (om == bm0 && oi < bi0)) { bm0 = om; bi0 = oi; }
  }
  if (lane == 0) g_idx[b * PP + pn] = bi0;
}

// ---- kernel 2b: t>=1 categorical, quad-chain scan with exact break -------
// 4 candidates per lane per iteration (i, i+32, i+64, i+96): 4 independent
// threefry chains in flight. No per-lane coarse gate (redundant with the
// break under sorted order; evaluating extra candidates is conservative —
// the reference argmax considers all 2048). Break votes on the chunk's first
// 32 positions; descending sort makes it exact for the whole 128-chunk.
__global__ void __launch_bounds__(256) categorical_kernel(unsigned k0, unsigned k1) {
  __shared__ float sv[PP];
  __shared__ int   si[PP];
  int b   = blockIdx.y;
  int tid = threadIdx.x;
  for (int i = tid; i < PP; i += 256) {
    sv[i] = g_sv_val[b * PP + i];
    si[i] = g_sv_idx[b * PP + i];
  }
  __syncthreads();

  int lane = tid & 31;
  int pn   = blockIdx.x * 8 + (tid >> 5);
  unsigned base = ((unsigned)(pn * BB + b)) << 11;  // * PP
  float best = g_floor[b];
  int   bi = 0x7FFFFFFF;
  for (int s = 0; s < PP; s += 128) {
    int i0 = s + lane;
    float l0 = sv[i0];
    // exact break: sorted desc => if all of the first 32 positions of this
    // chunk fail l+16>best, every later position fails too.
    if (!__any_sync(0xFFFFFFFFu, __fadd_rn(l0, G_HI) > best)) break;
    int i1 = i0 + 32, i2 = i0 + 64, i3 = i0 + 96;
    float l1 = sv[i1], l2 = sv[i2], l3 = sv[i3];
    unsigned x0 = (unsigned)si[i0], x1 = (unsigned)si[i1];
    unsigned x2 = (unsigned)si[i2], x3 = (unsigned)si[i3];
    unsigned r0 = pbits32(k0, k1, base + x0);   // four independent chains
    unsigned r1 = pbits32(k0, k1, base + x1);
    unsigned r2 = pbits32(k0, k1, base + x2);
    unsigned r3 = pbits32(k0, k1, base + x3);
    float f0 = bits_to_f01(r0), f1 = bits_to_f01(r1);
    float f2 = bits_to_f01(r2), f3 = bits_to_f01(r3);
    if (__fadd_rn(l0, gumbel_ub(f0)) >= best) {     // fine bound gates logf
      float v = __fadd_rn(gumbel_from_f(f0), l0);
      if (v > best || (v == best && (int)x0 < bi)) { best = v; bi = (int)x0; }
    }
    if (__fadd_rn(l1, gumbel_ub(f1)) >= best) {
      float v = __fadd_rn(gumbel_from_f(f1), l1);
      if (v > best || (v == best && (int)x1 < bi)) { best = v; bi = (int)x1; }
    }
    if (__fadd_rn(l2, gumbel_ub(f2)) >= best) {
      float v = __fadd_rn(gumbel_from_f(f2), l2);
      if (v > best || (v == best && (int)x2 < bi)) { best = v; bi = (int)x2; }
    }
    if (__fadd_rn(l3, gumbel_ub(f3)) >= best) {
      float v = __fadd_rn(gumbel_from_f(f3), l3);
      if (v > best || (v == best && (int)x3 < bi)) { best = v; bi = (int)x3; }
    }
  }
#pragma unroll
  for (int off = 16; off > 0; off >>= 1) {
    float ov = __shfl_down_sync(0xFFFFFFFFu, best, off);
    int   oi = __shfl_down_sync(0xFFFFFFFFu, bi,   off);
    if (ov > best || (ov == best && oi < bi)) { best = ov; bi = oi; }
  }
  if (lane == 0) g_idx[b * PP + pn] = bi;
}

// ---- kernel 3: fused resample-gather + transition + measurement ----------
// (R14 form: interleaved normal generation — the measured-fastest variant.)
__global__ void __launch_bounds__(256) update_kernel(
    unsigned kn0, unsigned kn1, int t,
    const float* __restrict__ obs, const float* __restrict__ init_p,
    const float* __restrict__ A, const float* __restrict__ bvec,
    const float* __restrict__ log_sigma, const float* __restrict__ Cm,
    const float* __restrict__ log_r,
    float* __restrict__ pseq, float* __restrict__ wseq, float c8) {
  __shared__ float4 sA[DD * DD / 4];   // 256 float4
  __shared__ float4 sC[DOB * DD / 4];  // 128 float4
  __shared__ float s_sig[DD], s_er[DOB];
  __shared__ float s_slr;
  int tid = threadIdx.x;
  for (int i = tid; i < DD * DD / 4; i += 256) sA[i] = ((const float4*)A)[i];
  for (int i = tid; i < DOB * DD / 4; i += 256) sC[i] = ((const float4*)Cm)[i];
  if (tid < DD)  s_sig[tid] = expf(log_sigma[tid]);
  if (tid < DOB) s_er[tid]  = expf(-log_r[tid]);
  if (tid == 0) {
    float a = 0.0f;
#pragma unroll
    for (int o = 0; o < DOB; ++o) a = __fadd_rn(a, log_r[o]);
    s_slr = a;
  }
  __syncthreads();

  int gid = blockIdx.x * 256 + tid;
  int b = gid >> 11;
  int p = gid & (PP - 1);
  int j = g_idx[b * PP + p];
  const float4* src4 = (t == 0)
      ? (const float4*)(init_p + ((size_t)b * PP + j) * DD)
      : (const float4*)(pseq + (((size_t)b * TT + (t - 1)) * PP + j) * DD);
  float x[DD];
#pragma unroll
  for (int q = 0; q < DD / 4; ++q) {
    float4 v = src4[q];
    x[4 * q] = v.x; x[4 * q + 1] = v.y; x[4 * q + 2] = v.z; x[4 * q + 3] = v.w;
  }

  float xn[DD];
  unsigned ibase = ((unsigned)(b * PP + p)) * DD;
#pragma unroll 4
  for (int e = 0; e < DD; ++e) {
    float mv = 0.0f;
#pragma unroll
    for (int q = 0; q < DD / 4; ++q) {
      float4 a = sA[e * (DD / 4) + q];
      mv = fmaf(x[4 * q],     a.x, mv);
      mv = fmaf(x[4 * q + 1], a.y, mv);
      mv = fmaf(x[4 * q + 2], a.z, mv);
      mv = fmaf(x[4 * q + 3], a.w, mv);
    }
    float n = normal_from_bits(pbits32(kn0, kn1, ibase + (unsigned)e));
    // ((dot + b) + noise*sigma): separate roundings, left-assoc like XLA
    xn[e] = __fadd_rn(__fadd_rn(mv, bvec[e]), __fmul_rn(n, s_sig[e]));
  }
  float4* out4 = (float4*)(pseq + (((size_t)b * TT + t) * PP + p) * DD);
#pragma unroll
  for (int q = 0; q < DD / 4; ++q)
    out4[q] = make_float4(xn[4 * q], xn[4 * q + 1], xn[4 * q + 2], xn[4 * q + 3]);

  const float* y = obs + ((size_t)b * TT + t) * DOB;
  float ss = 0.0f;
#pragma unroll
  for (int o = 0; o < DOB; ++o) {
    float mean = 0.0f;
#pragma unroll
    for (int q = 0; q < DD / 4; ++q) {
      float4 c = sC[o * (DD / 4) + q];
      mean = fmaf(xn[4 * q],     c.x, mean);
      mean = fmaf(xn[4 * q + 1], c.y, mean);
      mean = fmaf(xn[4 * q + 2], c.z, mean);
      mean = fmaf(xn[4 * q + 3], c.w, mean);
    }
    float rr = __fmul_rn(__fsub_rn(y[o], mean), s_er[o]);
    ss = __fadd_rn(ss, __fmul_rn(rr, rr));
  }
  float logw = __fsub_rn(__fsub_rn(__fmul_rn(-0.5f, ss), s_slr), c8);
  wseq[((size_t)b * TT + t) * PP + p] = logw;
}

// ---------------- host ----------------
extern "C" void kernel_launch(void* const* d_in, const int* in_sizes, int n_in,
                              void* d_out, int out_size) {
  (void)out_size;
  // Dispatch inputs by element count (robust to metadata ordering).
  const float *obs = 0, *init_p = 0, *A = 0, *bvec = 0, *lsig = 0, *Cm = 0, *lr = 0;
  for (int i = 0; i < n_in; ++i) {
    const float* ptr = (const float*)d_in[i];
    switch (in_sizes[i]) {
      case BB * TT * DOB:      obs = ptr;    break;  // 32768
      case BB * PP * DD:       init_p = ptr; break;  // 2097152
      case DD * DD:            A = ptr;      break;  // 1024
      case DOB * DD:           Cm = ptr;     break;  // 512
      case DOB:                lr = ptr;     break;  // 16
      case DD:  if (!bvec) bvec = ptr; else lsig = ptr; break;  // b, log_sigma
      default: break;
    }
  }
  float* pseq = (float*)d_out;
  float* wseq = pseq + PSEQ_ELEMS;

  // 0.5 * dim_obs * log(2*pi), f32 pipeline like XLA's constant folding
  float log2pi = logf(6.2831855f);
  float c8     = 8.0f * log2pi;

  for (int t = 0; t < TT; ++t) {
    // k = fold_in(key(42), t) = threefry((0,42),(0,t))
    unsigned h0, h1;
    tf2x32(0u, 42u, 0u, (unsigned)t, h0, h1);
    // partitionable foldlike split: key_i = threefry(k, (0, i)) both words
    unsigned r0a, r0b, r1a, r1b;
    tf2x32(h0, h1, 0u, 0u, r0a, r0b);   // k_res   = (r0a, r0b)
    tf2x32(h0, h1, 0u, 1u, r1a, r1b);   // k_noise = (r1a, r1b)

    if (t == 0) {
      categorical_t0_kernel<<<dim3(PP / 8, BB), 256>>>(r0a, r0b);
    } else {
      normalize_kernel<<<BB, 512>>>(wseq, t);
      categorical_kernel<<<dim3(PP / 8, BB), 256>>>(r0a, r0b);
    }
    update_kernel<<<(BB * PP) / 256, 256>>>(r1a, r1b, t, obs, init_p, A, bvec,
                                            lsig, Cm, lr, pseq, wseq, c8);
  }
}